// round 3
// baseline (speedup 1.0000x reference)
#include <cuda_runtime.h>

typedef unsigned long long u64;

// packed f32x2 helpers (sm_100+ PTX; doubles FFMA throughput)
__device__ __forceinline__ u64 pk2(float lo, float hi) {
    u64 r; asm("mov.b64 %0,{%1,%2};" : "=l"(r) : "f"(lo), "f"(hi)); return r;
}
__device__ __forceinline__ u64 fma2(u64 a, u64 b, u64 c) {
    u64 d; asm("fma.rn.f32x2 %0,%1,%2,%3;" : "=l"(d) : "l"(a), "l"(b), "l"(c)); return d;
}
__device__ __forceinline__ float sum2(u64 a) {
    float lo, hi; asm("mov.b64 {%0,%1},%2;" : "=f"(lo), "=f"(hi) : "l"(a)); return lo + hi;
}

// Scratch (allocation-free rule: __device__ globals)
__device__ float g_n1[2048 * 8];     // n1[row][k]
__device__ float g_n2T[6 * 2048];    // n2 transposed [k][row] -> coalesced reads in k_adj

// ---------------------------------------------------------------------------
// Merged: t = mean_h(wa) @ x ; gcn = relu(t@W^T+b) ; out = gcn@Wxx^T+b ;
//         n1 = gcn@Wn1^T ; n2 = gcn@Wn2^T
// grid = B*(L/8) = 256 blocks, 256 threads (two 128-thread halves)
// W / Wxx are staged per k-tile into smem with an in-block transpose
// (coalesced global reads; stride-129 smem writes -> conflict-free).
// ---------------------------------------------------------------------------
__global__ void __launch_bounds__(256) k_gcn(const float* __restrict__ x,
                                             const float* __restrict__ wa,
                                             const float* __restrict__ Ww,
                                             const float* __restrict__ Wb,
                                             const float* __restrict__ Wx_w,
                                             const float* __restrict__ Wxx,
                                             const float* __restrict__ Wxxb,
                                             float* __restrict__ out) {
    __shared__ __align__(16) float pool[8192];    // x tiles -> t partials -> w tiles
    __shared__ __align__(16) float a_s[2][256];
    __shared__ __align__(16) float t_s[1024];
    __shared__ __align__(16) float g_s[1024];

    int b    = blockIdx.x >> 5;
    int i0   = (blockIdx.x & 31) << 3;
    int tid  = threadIdx.x;
    int lane = tid & 127;
    int half = tid >> 7;
    int r0   = blockIdx.x * 8;
    const float inv6 = 1.0f / 6.0f;

    // ---------- Phase A: t = mean_h(wa) @ x, halves split the j-range ----------
    float* x_s = pool + half * 4096;
    u64 acc2[8];
    #pragma unroll
    for (int ii = 0; ii < 8; ii++) acc2[ii] = 0ull;

    for (int jt = 0; jt < 4; jt++) {
        int j0 = half * 128 + jt * 32;
        const float4* xs = (const float4*)(x + ((long)b * 256 + j0) * 128);
        float4*       xd = (float4*)x_s;
        #pragma unroll
        for (int idx = lane; idx < 1024; idx += 128) xd[idx] = xs[idx];
        #pragma unroll
        for (int ent = lane; ent < 256; ent += 128) {
            int ii = ent >> 5, jj = ent & 31;
            float s = 0.0f;
            #pragma unroll
            for (int h = 0; h < 6; h++)
                s += wa[(((long)(b * 6 + h) * 256) + i0 + ii) * 256 + j0 + jj];
            a_s[half][ent] = s * inv6;
        }
        __syncthreads();
        #pragma unroll
        for (int g = 0; g < 32; g += 4) {
            float xv0 = x_s[(g + 0) * 128 + lane];
            float xv1 = x_s[(g + 1) * 128 + lane];
            float xv2 = x_s[(g + 2) * 128 + lane];
            float xv3 = x_s[(g + 3) * 128 + lane];
            u64 xp0 = pk2(xv0, xv1), xp1 = pk2(xv2, xv3);
            #pragma unroll
            for (int ii = 0; ii < 8; ii++) {
                const u64* ap = (const u64*)&a_s[half][ii * 32 + g];   // broadcast LDS.64
                acc2[ii] = fma2(ap[0], xp0, acc2[ii]);
                acc2[ii] = fma2(ap[1], xp1, acc2[ii]);
            }
        }
        __syncthreads();
    }
    // reduce the two halves via pool
    #pragma unroll
    for (int ii = 0; ii < 8; ii++) pool[half * 1024 + ii * 128 + lane] = sum2(acc2[ii]);
    __syncthreads();
    #pragma unroll
    for (int idx = tid; idx < 1024; idx += 256) t_s[idx] = pool[idx] + pool[1024 + idx];
    __syncthreads();

    // ---------- Phase B: gcn = relu(t @ Ww^T + b), halves split rows ----------
    float* w_s = pool;   // 32 x 129 tile, conflict-free transpose staging
    u64 b2[4];
    #pragma unroll
    for (int r = 0; r < 4; r++) b2[r] = 0ull;
    for (int kt = 0; kt < 4; kt++) {
        int k0 = kt * 32;
        #pragma unroll
        for (int idx = tid; idx < 4096; idx += 256) {
            int d = idx >> 5, c = idx & 31;
            w_s[c * 129 + d] = Ww[d * 128 + k0 + c];   // coalesced read, cf write
        }
        __syncthreads();
        #pragma unroll
        for (int kk = 0; kk < 32; kk += 2) {
            u64 wp = pk2(w_s[kk * 129 + lane], w_s[(kk + 1) * 129 + lane]);
            #pragma unroll
            for (int r = 0; r < 4; r++) {
                u64 t2 = *(const u64*)&t_s[(half * 4 + r) * 128 + k0 + kk];  // broadcast
                b2[r] = fma2(t2, wp, b2[r]);
            }
        }
        __syncthreads();
    }
    float bb = Wb[lane];
    #pragma unroll
    for (int r = 0; r < 4; r++)
        g_s[(half * 4 + r) * 128 + lane] = fmaxf(sum2(b2[r]) + bb, 0.0f);
    __syncthreads();

    // ---------- Phase C: out = gcn @ Wxx^T + b ----------
    u64 o2[4];
    #pragma unroll
    for (int r = 0; r < 4; r++) o2[r] = 0ull;
    for (int kt = 0; kt < 4; kt++) {
        int k0 = kt * 32;
        #pragma unroll
        for (int idx = tid; idx < 4096; idx += 256) {
            int d = idx >> 5, c = idx & 31;
            w_s[c * 129 + d] = Wxx[d * 128 + k0 + c];
        }
        __syncthreads();
        #pragma unroll
        for (int kk = 0; kk < 32; kk += 2) {
            u64 wp = pk2(w_s[kk * 129 + lane], w_s[(kk + 1) * 129 + lane]);
            #pragma unroll
            for (int r = 0; r < 4; r++) {
                u64 g2 = *(const u64*)&g_s[(half * 4 + r) * 128 + k0 + kk];
                o2[r] = fma2(g2, wp, o2[r]);
            }
        }
        __syncthreads();
    }
    float ob = Wxxb[lane];
    #pragma unroll
    for (int r = 0; r < 4; r++)
        out[(long)(r0 + half * 4 + r) * 128 + lane] = sum2(o2[r]) + ob;

    // ---------- Phase D: n1/n2 — 96 dots of length 128 ----------
    if (tid < 96) {
        int sel = tid / 48;                 // 0 -> n1, 1 -> n2
        int q   = tid - sel * 48;
        int r   = q / 6, k = q % 6;
        const float* g = &g_s[r * 128];
        const float* w = Wx_w + k * 294 + 6 + sel * 128;
        u64 s = 0ull;
        #pragma unroll 8
        for (int d = 0; d < 128; d += 2)
            s = fma2(*(const u64*)&g[d], pk2(__ldg(&w[d]), __ldg(&w[d + 1])), s);
        float v = sum2(s);
        if (sel == 0) g_n1[(r0 + r) * 8 + k]   = v;
        else          g_n2T[k * 2048 + r0 + r] = v;
    }
}

// ---------------------------------------------------------------------------
// new_adj[b,k,i,j] = sum_h wa[b,h,i,j]*Wa[k,h] + n1[b,i,k] + n2[b,j,k]
//                  + sum_e e[b,i,j,e]*We[k,e] + Wx_b[k]
// grid = B*L = 2048 blocks (one per (b,i)), 256 threads (thread = j)
// ---------------------------------------------------------------------------
__global__ void __launch_bounds__(256) k_adj(const float* __restrict__ wa,
                                             const float* __restrict__ e,
                                             const float* __restrict__ Wx_w,
                                             const float* __restrict__ Wx_b,
                                             float* __restrict__ adj_out) {
    __shared__ __align__(16) float e_s[256 * 36];  // [j][ee] pad 36: .128 both sides, cf
    __shared__ __align__(16) float Wa_s[40];       // [k*6+h]
    __shared__ __align__(16) float We_s[200];      // [k*32+ee]
    __shared__ __align__(16) float n1b_s[16];      // n1 @0..5, bias @8..13
    int b   = blockIdx.x >> 8;
    int i   = blockIdx.x & 255;
    int tid = threadIdx.x;

    // front-batched e loads: 8 independent LDG.128 in flight (MLP)
    const float4* e4 = (const float4*)(e + (((long)b * 256 + i) * 256) * 32);
    float4 v[8];
    #pragma unroll
    for (int it = 0; it < 8; it++) v[it] = e4[tid + it * 256];

    float wv[6];
    #pragma unroll
    for (int h = 0; h < 6; h++)
        wv[h] = wa[(((long)(b * 6 + h) * 256) + i) * 256 + tid];

    float n2v[6];
    #pragma unroll
    for (int k = 0; k < 6; k++) n2v[k] = g_n2T[k * 2048 + b * 256 + tid];

    if (tid < 36) Wa_s[tid] = Wx_w[(tid / 6) * 294 + tid % 6];
    if (tid >= 64 && tid < 256) {
        int t = tid - 64;
        We_s[t] = Wx_w[(t >> 5) * 294 + 262 + (t & 31)];
    }
    if (tid >= 40 && tid < 46) n1b_s[tid - 40]     = g_n1[((long)b * 256 + i) * 8 + (tid - 40)];
    if (tid >= 48 && tid < 54) n1b_s[8 + tid - 48] = Wx_b[tid - 48];

    #pragma unroll
    for (int it = 0; it < 8; it++) {
        int idx = tid + it * 256;
        *(float4*)&e_s[(idx >> 3) * 36 + (idx & 7) * 4] = v[it];
    }
    __syncthreads();

    u64 acc2[6];
    #pragma unroll
    for (int k = 0; k < 6; k++) acc2[k] = 0ull;

    // adj term: 3 packed h-pairs x 6 k
    u64 wp0 = pk2(wv[0], wv[1]), wp1 = pk2(wv[2], wv[3]), wp2 = pk2(wv[4], wv[5]);
    #pragma unroll
    for (int k = 0; k < 6; k++) {
        acc2[k] = fma2(*(const u64*)&Wa_s[k * 6 + 0], wp0, acc2[k]);
        acc2[k] = fma2(*(const u64*)&Wa_s[k * 6 + 2], wp1, acc2[k]);
        acc2[k] = fma2(*(const u64*)&Wa_s[k * 6 + 4], wp2, acc2[k]);
    }

    // e term: 8 x LDS.128 (conflict-free), 16 packed ee-pairs x 6 k
    const float4* ep = (const float4*)&e_s[tid * 36];
    #pragma unroll
    for (int q = 0; q < 8; q++) {
        float4 w = ep[q];
        u64 ev0 = pk2(w.x, w.y);
        u64 ev1 = pk2(w.z, w.w);
        #pragma unroll
        for (int k = 0; k < 6; k++) {
            acc2[k] = fma2(ev0, *(const u64*)&We_s[k * 32 + q * 4 + 0], acc2[k]);
            acc2[k] = fma2(ev1, *(const u64*)&We_s[k * 32 + q * 4 + 2], acc2[k]);
        }
    }

    long ob = ((long)(b * 6) * 65536) + (long)i * 256 + tid;
    #pragma unroll
    for (int k = 0; k < 6; k++)
        adj_out[ob + (long)k * 65536] = sum2(acc2[k]) + n1b_s[k] + n1b_s[8 + k] + n2v[k];
}

// ---------------------------------------------------------------------------
extern "C" void kernel_launch(void* const* d_in, const int* in_sizes, int n_in,
                              void* d_out, int out_size) {
    const float* x     = (const float*)d_in[0];
    const float* wa    = (const float*)d_in[1];
    const float* e     = (const float*)d_in[2];
    const float* W_w   = (const float*)d_in[3];
    const float* W_b   = (const float*)d_in[4];
    const float* Wx_w  = (const float*)d_in[5];
    const float* Wx_b  = (const float*)d_in[6];
    const float* Wxx_w = (const float*)d_in[7];
    const float* Wxx_b = (const float*)d_in[8];

    float* out     = (float*)d_out;            // (B,L,D) = 262144 floats
    float* adj_out = out + 8 * 256 * 128;      // (B,H,L,L) = 3145728 floats

    k_gcn<<<256, 256>>>(x, wa, W_w, W_b, Wx_w, Wxx_w, Wxx_b, out);
    k_adj<<<2048, 256>>>(wa, e, Wx_w, Wx_b, adj_out);
}